// round 8
// baseline (speedup 1.0000x reference)
#include <cuda_runtime.h>
#include <cuda_fp16.h>
#include <cstdint>
#include <math.h>

#define T 512
#define TP 520            /* T + 8 zero-pad rows for dw-shifted B reads */
#define B 128
#define H 512
#define NF 128
#define FS 5
#define W_ELEMS 983040    /* 128 * 512 * 15 */
#define PAD_ELEMS 524288  /* B * 8 * H */
#define FEAT_ELEMS 81920  /* B * 5 * NF */

// ---------------------------------------------------------------------------
// Scratch (__device__ globals: allocation-guard safe)
// ---------------------------------------------------------------------------
__device__ __align__(16) __half g_W[W_ELEMS];                 // [sec w][f][k=dw*512+h]
__device__ __align__(16) __half g_X[(size_t)B * TP * H];      // X fp16 [b][t][h]
__device__ float g_feat[(size_t)B * 5 * NF];                  // pooled features
__device__ float g_v[5 * NF];                                 // collapsed fc vector
__device__ float g_c[1];                                      // collapsed fc scalar

// ---------------------------------------------------------------------------
// Portable PTX helpers (valid at compute_103 virtual arch)
// ---------------------------------------------------------------------------
__device__ __forceinline__ uint32_t smem_to_u32(const void* p) {
    uint32_t a;
    asm("{ .reg .u64 t; cvta.to.shared.u64 t, %1; cvt.u32.u64 %0, t; }" : "=r"(a) : "l"(p));
    return a;
}
#define SMEM_SWIZZLE_128B(off) ((off) ^ (((off) >> 3) & 0x70))

#define CP_ASYNC_16(dst, src) \
    asm volatile("cp.async.cg.shared.global [%0], [%1], 16;" :: "r"(dst), "l"(src))
#define CP_ASYNC_COMMIT() asm volatile("cp.async.commit_group;" ::: "memory")
#define CP_ASYNC_WAIT(n)  asm volatile("cp.async.wait_group %0;" :: "n"(n) : "memory")

__device__ __forceinline__ void ldsm_x4(uint32_t* r, uint32_t addr) {
    asm volatile("ldmatrix.sync.aligned.m8n8.x4.shared.b16 {%0,%1,%2,%3}, [%4];"
                 : "=r"(r[0]), "=r"(r[1]), "=r"(r[2]), "=r"(r[3]) : "r"(addr));
}

__device__ __forceinline__ void mma_f16(float* c, const uint32_t* a, const uint32_t* b) {
    asm volatile(
        "mma.sync.aligned.m16n8k16.row.col.f32.f16.f16.f32 "
        "{%0,%1,%2,%3}, {%4,%5,%6,%7}, {%8,%9}, {%0,%1,%2,%3};"
        : "+f"(c[0]), "+f"(c[1]), "+f"(c[2]), "+f"(c[3])
        : "r"(a[0]), "r"(a[1]), "r"(a[2]), "r"(a[3]), "r"(b[0]), "r"(b[1]));
}

// ---------------------------------------------------------------------------
// Combined prep kernel. grid (16, 4, 228), block 256.
//  z <  128 : gather+transpose pack of X for batch z; 4 h-subtiles per block
//  z >= 128 : linearized aux: W pack | pad-row zero | feat zero | fc collapse
// ---------------------------------------------------------------------------
__global__ void __launch_bounds__(256) prep_kernel(
    const float* __restrict__ enc, const int* __restrict__ lengths,
    const float* __restrict__ w1, const float* __restrict__ w2,
    const float* __restrict__ w3, const float* __restrict__ w4,
    const float* __restrict__ w5,
    const float* __restrict__ fc1_w, const float* __restrict__ fc1_b,
    const float* __restrict__ fc2_w, const float* __restrict__ fc2_b)
{
    int z = blockIdx.z;
    int tid = threadIdx.x;

    if (z < B) {
        // ---- pack_xt path: tile 32(t) x 128(h) per block, 4 subtiles ----
        __shared__ float tile[32][33];
        int b  = z;
        int L  = lengths[b];
        int Leff = (L > FS) ? L : FS;
        int t0 = blockIdx.x * 32;
        if (t0 >= Leff) return;     // masked-out tiles: stale data harmless
        int wid = tid >> 5, lane = tid & 31;
        int t = t0 + lane;
        size_t encb = (size_t)b * H;

        #pragma unroll 1
        for (int hs = 0; hs < 4; hs++) {
            int h0 = blockIdx.y * 128 + hs * 32;
            #pragma unroll
            for (int k = 0; k < 4; k++) {
                int hl = wid * 4 + k;
                float v = 0.0f;
                if (t < L) {
                    int i = (h0 + hl) * L + t;
                    v = enc[(size_t)(i >> 9) * (B * H) + encb + (i & (H - 1))];
                }
                tile[hl][lane] = v;
            }
            __syncthreads();
            // transposed half2 writes: 2 rows per warp per iter, 16 lanes/row
            #pragma unroll
            for (int it = 0; it < 2; it++) {
                int tl = it * 16 + wid * 2 + (lane >> 4);
                int hh = (lane & 15) * 2;
                __half2 val = __floats2half2_rn(tile[hh][tl], tile[hh + 1][tl]);
                *(__half2*)&g_X[((size_t)b * TP + t0 + tl) * H + h0 + hh] = val;
            }
            __syncthreads();
        }
        return;
    }

    // ---- aux path ----
    int bi = (z - B) * 64 + blockIdx.y * 16 + blockIdx.x;    // 0..6399
    int g  = bi * 256 + tid;

    if (g < W_ELEMS) {
        int idx = g;
        int w, rel;
        if (idx < 65536)       { w = 1; rel = idx; }
        else if (idx < 196608) { w = 2; rel = idx - 65536; }
        else if (idx < 393216) { w = 3; rel = idx - 196608; }
        else if (idx < 655360) { w = 4; rel = idx - 393216; }
        else                   { w = 5; rel = idx - 655360; }
        int Kw = w << 9;
        int f  = rel / Kw;
        int k  = rel - f * Kw;
        int dw = k >> 9;
        int h  = k & 511;
        const float* wp = (w == 1) ? w1 : (w == 2) ? w2 : (w == 3) ? w3 : (w == 4) ? w4 : w5;
        g_W[idx] = __float2half(wp[(size_t)(f * H + h) * w + dw]);
        return;
    }
    int r = g - W_ELEMS;
    if (r < PAD_ELEMS) {            // zero the 8 pad rows per batch
        int b   = r >> 12;          // /(8*H)
        int off = r & 4095;
        g_X[(size_t)b * TP * H + (size_t)T * H + off] = __float2half(0.0f);
        return;
    }
    r -= PAD_ELEMS;
    if (r < FEAT_ELEMS) { g_feat[r] = 0.0f; return; }
    r -= FEAT_ELEMS;
    if (r < 5 * NF) {               // fc collapse: v[j] = sum_o fc2_w[o] * fc1_w[o][j]
        float s = 0.0f;
        #pragma unroll 4
        for (int o = 0; o < 100; o++) s += fc2_w[o] * fc1_w[(size_t)o * (5 * NF) + r];
        g_v[r] = s;
        if (r == 0) {
            float c = fc2_b[0];
            for (int o = 0; o < 100; o++) c += fc2_w[o] * fc1_b[o];
            g_c[0] = c;
        }
    }
}

// ---------------------------------------------------------------------------
// Fused conv-GEMM + bias + relu + masked max-pool (single-pass fp16).
// Section w: out(f,t) = sum_{dw<w, h} W[f,h,dw] * X[h, t+dw]  (K = 512*w)
// CTA tile 128(f) x 128(t), warp tile 64x32, K-chunk 64, 3-stage cp.async.
// Dead 8-col slabs (base t > tmax) skip ldsm+MMA at ni granularity.
// LPT order: blockIdx.z slowest = w, with w=5 scheduled first.
// ---------------------------------------------------------------------------
#define GEMM_SMEM_BYTES 98304

__global__ void __launch_bounds__(256) gemm_kernel(
    const int* __restrict__ lengths,
    const float* __restrict__ b1, const float* __restrict__ b2,
    const float* __restrict__ b3, const float* __restrict__ b4,
    const float* __restrict__ b5)
{
    extern __shared__ char smem[];
    int b = blockIdx.y;
    int w = 5 - blockIdx.z;            // LPT: longest CTAs (w=5) launch first
    int L = lengths[b];
    int Leff = (L > FS) ? L : FS;
    int tmax = Leff - w;               // inclusive valid t
    int t0 = blockIdx.x * 128;
    if (t0 > tmax) return;

    const int soff_tab[5] = { 0, 65536, 196608, 393216, 655360 };
    const __half* Abase = g_W + soff_tab[w - 1];
    int Kw  = w << 9;
    int nch = w << 3;                  // K / 64

    uint32_t sb = smem_to_u32(smem);
    int tid = threadIdx.x, wid = tid >> 5, lane = tid & 31;
    int wm = wid >> 2;                 // 0..1 : rows wm*64
    int wn = wid & 3;                  // 0..3 : cols wn*32

    // valid 8-col slabs for this warp (uniform): ni valid iff t0+wn*32+ni*8 <= tmax
    int rel = tmax - t0 - wn * 32;
    int cnt = (rel < 0) ? 0 : ((rel >> 3) + 1);
    if (cnt > 4) cnt = 4;
    int nhcnt = (cnt + 1) >> 1;        // 16-col ldsm groups needed

    const __half* XB = g_X + ((size_t)b * TP + t0) * H;

    auto load_stage = [&](int c, int s) {
        uint32_t st = sb + (uint32_t)s * 32768u;
        int dw = c >> 3, cc = c & 7;
        #pragma unroll
        for (int q = 0; q < 4; q++) {
            int idx  = q * 256 + tid;  // 0..1023
            int row  = idx >> 3;       // 0..127
            int col8 = idx & 7;
            uint32_t sw = SMEM_SWIZZLE_128B((uint32_t)(row * 128 + col8 * 16));
            CP_ASYNC_16(st + sw,          Abase + (size_t)row * Kw + c * 64 + col8 * 8);
            CP_ASYNC_16(st + 16384u + sw, XB + (size_t)(dw + row) * H + cc * 64 + col8 * 8);
        }
        CP_ASYNC_COMMIT();
    };

    float acc[4][4][4];
    #pragma unroll
    for (int mi = 0; mi < 4; mi++)
        #pragma unroll
        for (int ni = 0; ni < 4; ni++)
            #pragma unroll
            for (int e = 0; e < 4; e++) acc[mi][ni][e] = 0.0f;

    load_stage(0, 0);
    load_stage(1, 1);

    #pragma unroll 1
    for (int c = 0; c < nch; c++) {
        if (c + 2 < nch) { load_stage(c + 2, (c + 2) % 3); CP_ASYNC_WAIT(2); }
        else             { CP_ASYNC_WAIT(0); }
        __syncthreads();

        if (cnt > 0) {
            uint32_t st = sb + (uint32_t)(c % 3) * 32768u;
            #pragma unroll
            for (int ks = 0; ks < 4; ks++) {
                int k0 = ks * 16;
                uint32_t a[4][4];
                #pragma unroll
                for (int mi = 0; mi < 4; mi++) {
                    int row = wm * 64 + mi * 16 + ((lane >> 3) & 1) * 8 + (lane & 7);
                    int col = k0 + (lane >> 4) * 8;
                    ldsm_x4(a[mi], st + SMEM_SWIZZLE_128B((uint32_t)(row * 128 + col * 2)));
                }
                uint32_t bh[2][4];
                #pragma unroll
                for (int nh = 0; nh < 2; nh++) {
                    if (nh < nhcnt) {
                        int row = wn * 32 + nh * 16 + (lane >> 4) * 8 + (lane & 7);
                        int col = k0 + ((lane >> 3) & 1) * 8;
                        ldsm_x4(bh[nh], st + 16384u + SMEM_SWIZZLE_128B((uint32_t)(row * 128 + col * 2)));
                    }
                }
                #pragma unroll
                for (int mi = 0; mi < 4; mi++)
                    #pragma unroll
                    for (int ni = 0; ni < 4; ni++)
                        if (ni < cnt)
                            mma_f16(acc[mi][ni], a[mi], &bh[ni >> 1][(ni & 1) * 2]);
            }
        }
        __syncthreads();
    }

    // Epilogue: masked max over t, + bias, relu floor, atomicMax into g_feat.
    const float* bias = (w == 1) ? b1 : (w == 2) ? b2 : (w == 3) ? b3 : (w == 4) ? b4 : b5;
    float* featb = g_feat + (size_t)b * (5 * NF) + (size_t)(w - 1) * NF;

    #pragma unroll
    for (int mi = 0; mi < 4; mi++) {
        int f0 = wm * 64 + mi * 16 + (lane >> 2);
        float m0 = -1e30f, m1 = -1e30f;
        #pragma unroll
        for (int ni = 0; ni < 4; ni++) {
            int t = t0 + wn * 32 + ni * 8 + (lane & 3) * 2;
            if (t <= tmax)     { m0 = fmaxf(m0, acc[mi][ni][0]); m1 = fmaxf(m1, acc[mi][ni][2]); }
            if (t + 1 <= tmax) { m0 = fmaxf(m0, acc[mi][ni][1]); m1 = fmaxf(m1, acc[mi][ni][3]); }
        }
        #pragma unroll
        for (int o = 1; o <= 2; o <<= 1) {
            m0 = fmaxf(m0, __shfl_xor_sync(0xffffffffu, m0, o));
            m1 = fmaxf(m1, __shfl_xor_sync(0xffffffffu, m1, o));
        }
        if ((lane & 3) == 0) {
            float fa = fmaxf(0.0f, m0 + bias[f0]);
            float fb = fmaxf(0.0f, m1 + bias[f0 + 8]);
            atomicMax((int*)&featb[f0],     __float_as_int(fa));
            atomicMax((int*)&featb[f0 + 8], __float_as_int(fb));
        }
    }
}

// ---------------------------------------------------------------------------
// Collapsed FC: out[b] = sigmoid(feat_b . g_v + g_c). One warp per batch.
// ---------------------------------------------------------------------------
__global__ void __launch_bounds__(1024) fc_kernel(float* __restrict__ out) {
    int warp = threadIdx.x >> 5, lane = threadIdx.x & 31;
    int b = blockIdx.x * 32 + warp;
    if (b >= B) return;
    const float* feat = g_feat + (size_t)b * (5 * NF);
    float s = 0.0f;
    #pragma unroll
    for (int k = 0; k < 20; k++) {
        int j = k * 32 + lane;
        s += feat[j] * g_v[j];
    }
    #pragma unroll
    for (int off = 16; off > 0; off >>= 1)
        s += __shfl_xor_sync(0xffffffffu, s, off);
    if (lane == 0) out[b] = 1.0f / (1.0f + expf(-(s + g_c[0])));
}

// ---------------------------------------------------------------------------
extern "C" void kernel_launch(void* const* d_in, const int* in_sizes, int n_in,
                              void* d_out, int out_size) {
    const float* enc     = (const float*)d_in[0];
    const int*   lengths = (const int*)d_in[1];
    const float* w1 = (const float*)d_in[2];
    const float* cb1 = (const float*)d_in[3];
    const float* w2 = (const float*)d_in[4];
    const float* cb2 = (const float*)d_in[5];
    const float* w3 = (const float*)d_in[6];
    const float* cb3 = (const float*)d_in[7];
    const float* w4 = (const float*)d_in[8];
    const float* cb4 = (const float*)d_in[9];
    const float* w5 = (const float*)d_in[10];
    const float* cb5 = (const float*)d_in[11];
    const float* fc1_w = (const float*)d_in[12];
    const float* fc1_b = (const float*)d_in[13];
    const float* fc2_w = (const float*)d_in[14];
    const float* fc2_b = (const float*)d_in[15];
    float* out = (float*)d_out;

    static bool s_attr_done = false;
    if (!s_attr_done) {
        cudaFuncSetAttribute(gemm_kernel, cudaFuncAttributeMaxDynamicSharedMemorySize,
                             GEMM_SMEM_BYTES);
        s_attr_done = true;
    }

    prep_kernel<<<dim3(16, 4, 228), 256>>>(enc, lengths, w1, w2, w3, w4, w5,
                                           fc1_w, fc1_b, fc2_w, fc2_b);
    gemm_kernel<<<dim3(T / 128, B, 5), 256, GEMM_SMEM_BYTES>>>(lengths, cb1, cb2, cb3, cb4, cb5);
    fc_kernel<<<4, 1024>>>(out);
}

// round 11
// speedup vs baseline: 1.0927x; 1.0927x over previous
#include <cuda_runtime.h>
#include <cuda_fp16.h>
#include <cstdint>
#include <math.h>

#define T 512
#define TP 520            /* T + 8 zero-pad rows for dw-shifted B reads */
#define B 128
#define H 512
#define NF 128
#define FS 5
#define W_ELEMS 983040    /* 128 * 512 * 15 */
#define PAD_ELEMS 524288  /* B * 8 * H */
#define FEAT_ELEMS 81920  /* B * 5 * NF */

// ---------------------------------------------------------------------------
// Scratch (__device__ globals: allocation-guard safe)
// ---------------------------------------------------------------------------
__device__ __align__(16) __half g_W[W_ELEMS];                 // [sec w][f][k=dw*512+h]
__device__ __align__(16) __half g_X[(size_t)B * TP * H];      // X fp16 [b][t][h]
__device__ float g_feat[(size_t)B * 5 * NF];                  // pooled features
__device__ float g_v[5 * NF];                                 // collapsed fc vector
__device__ float g_c[1];                                      // collapsed fc scalar

// ---------------------------------------------------------------------------
// Portable PTX helpers (valid at compute_103 virtual arch)
// ---------------------------------------------------------------------------
__device__ __forceinline__ uint32_t smem_to_u32(const void* p) {
    uint32_t a;
    asm("{ .reg .u64 t; cvta.to.shared.u64 t, %1; cvt.u32.u64 %0, t; }" : "=r"(a) : "l"(p));
    return a;
}
#define SMEM_SWIZZLE_128B(off) ((off) ^ (((off) >> 3) & 0x70))

#define CP_ASYNC_16(dst, src) \
    asm volatile("cp.async.cg.shared.global [%0], [%1], 16;" :: "r"(dst), "l"(src))
#define CP_ASYNC_COMMIT() asm volatile("cp.async.commit_group;" ::: "memory")
#define CP_ASYNC_WAIT(n)  asm volatile("cp.async.wait_group %0;" :: "n"(n) : "memory")

__device__ __forceinline__ void ldsm_x4(uint32_t* r, uint32_t addr) {
    asm volatile("ldmatrix.sync.aligned.m8n8.x4.shared.b16 {%0,%1,%2,%3}, [%4];"
                 : "=r"(r[0]), "=r"(r[1]), "=r"(r[2]), "=r"(r[3]) : "r"(addr));
}

__device__ __forceinline__ void mma_f16(float* c, const uint32_t* a, const uint32_t* b) {
    asm volatile(
        "mma.sync.aligned.m16n8k16.row.col.f32.f16.f16.f32 "
        "{%0,%1,%2,%3}, {%4,%5,%6,%7}, {%8,%9}, {%0,%1,%2,%3};"
        : "+f"(c[0]), "+f"(c[1]), "+f"(c[2]), "+f"(c[3])
        : "r"(a[0]), "r"(a[1]), "r"(a[2]), "r"(a[3]), "r"(b[0]), "r"(b[1]));
}

// ---------------------------------------------------------------------------
// Combined prep kernel. grid (16, 4, 228), block 256.  [Round-8 measured-good]
//  z <  128 : gather+transpose pack of X for batch z; 4 h-subtiles per block
//  z >= 128 : linearized aux: W pack | pad-row zero | feat zero | fc collapse
// ---------------------------------------------------------------------------
__global__ void __launch_bounds__(256) prep_kernel(
    const float* __restrict__ enc, const int* __restrict__ lengths,
    const float* __restrict__ w1, const float* __restrict__ w2,
    const float* __restrict__ w3, const float* __restrict__ w4,
    const float* __restrict__ w5,
    const float* __restrict__ fc1_w, const float* __restrict__ fc1_b,
    const float* __restrict__ fc2_w, const float* __restrict__ fc2_b)
{
    int z = blockIdx.z;
    int tid = threadIdx.x;

    if (z < B) {
        // ---- pack_xt path: tile 32(t) x 128(h) per block, 4 subtiles ----
        __shared__ float tile[32][33];
        int b  = z;
        int L  = lengths[b];
        int Leff = (L > FS) ? L : FS;
        int t0 = blockIdx.x * 32;
        if (t0 >= Leff) return;     // masked-out tiles: stale data harmless
        int wid = tid >> 5, lane = tid & 31;
        int t = t0 + lane;
        size_t encb = (size_t)b * H;

        #pragma unroll 1
        for (int hs = 0; hs < 4; hs++) {
            int h0 = blockIdx.y * 128 + hs * 32;
            #pragma unroll
            for (int k = 0; k < 4; k++) {
                int hl = wid * 4 + k;
                float v = 0.0f;
                if (t < L) {
                    int i = (h0 + hl) * L + t;
                    v = enc[(size_t)(i >> 9) * (B * H) + encb + (i & (H - 1))];
                }
                tile[hl][lane] = v;
            }
            __syncthreads();
            // transposed half2 writes: 2 rows per warp per iter, 16 lanes/row
            #pragma unroll
            for (int it = 0; it < 2; it++) {
                int tl = it * 16 + wid * 2 + (lane >> 4);
                int hh = (lane & 15) * 2;
                __half2 val = __floats2half2_rn(tile[hh][tl], tile[hh + 1][tl]);
                *(__half2*)&g_X[((size_t)b * TP + t0 + tl) * H + h0 + hh] = val;
            }
            __syncthreads();
        }
        return;
    }

    // ---- aux path ----
    int bi = (z - B) * 64 + blockIdx.y * 16 + blockIdx.x;    // 0..6399
    int g  = bi * 256 + tid;

    if (g < W_ELEMS) {
        int idx = g;
        int w, rel;
        if (idx < 65536)       { w = 1; rel = idx; }
        else if (idx < 196608) { w = 2; rel = idx - 65536; }
        else if (idx < 393216) { w = 3; rel = idx - 196608; }
        else if (idx < 655360) { w = 4; rel = idx - 393216; }
        else                   { w = 5; rel = idx - 655360; }
        int Kw = w << 9;
        int f  = rel / Kw;
        int k  = rel - f * Kw;
        int dw = k >> 9;
        int h  = k & 511;
        const float* wp = (w == 1) ? w1 : (w == 2) ? w2 : (w == 3) ? w3 : (w == 4) ? w4 : w5;
        g_W[idx] = __float2half(wp[(size_t)(f * H + h) * w + dw]);
        return;
    }
    int r = g - W_ELEMS;
    if (r < PAD_ELEMS) {            // zero the 8 pad rows per batch
        int b   = r >> 12;          // /(8*H)
        int off = r & 4095;
        g_X[(size_t)b * TP * H + (size_t)T * H + off] = __float2half(0.0f);
        return;
    }
    r -= PAD_ELEMS;
    if (r < FEAT_ELEMS) { g_feat[r] = 0.0f; return; }
    r -= FEAT_ELEMS;
    if (r < 5 * NF) {               // fc collapse: v[j] = sum_o fc2_w[o] * fc1_w[o][j]
        float s = 0.0f;
        #pragma unroll 4
        for (int o = 0; o < 100; o++) s += fc2_w[o] * fc1_w[(size_t)o * (5 * NF) + r];
        g_v[r] = s;
        if (r == 0) {
            float c = fc2_b[0];
            for (int o = 0; o < 100; o++) c += fc2_w[o] * fc1_b[o];
            g_c[0] = c;
        }
    }
}

// ---------------------------------------------------------------------------
// Fused conv-GEMM + bias + relu + masked max-pool (single-pass fp16).
// [Round-7 measured-good inner loop: fully unconditional, no warp skip]
// Section w: out(f,t) = sum_{dw<w, h} W[f,h,dw] * X[h, t+dw]  (K = 512*w)
// CTA tile 128(f) x 128(t), warp tile 64x32, K-chunk 64, 3-stage cp.async.
// LPT order: blockIdx.z slowest = w, with w=5 scheduled first.
// ---------------------------------------------------------------------------
#define GEMM_SMEM_BYTES 98304

__global__ void __launch_bounds__(256) gemm_kernel(
    const int* __restrict__ lengths,
    const float* __restrict__ b1, const float* __restrict__ b2,
    const float* __restrict__ b3, const float* __restrict__ b4,
    const float* __restrict__ b5)
{
    extern __shared__ char smem[];
    int b = blockIdx.y;
    int w = 5 - blockIdx.z;            // LPT: longest CTAs (w=5) launch first
    int L = lengths[b];
    int Leff = (L > FS) ? L : FS;
    int tmax = Leff - w;               // inclusive valid t
    int t0 = blockIdx.x * 128;
    if (t0 > tmax) return;

    const int soff_tab[5] = { 0, 65536, 196608, 393216, 655360 };
    const __half* Abase = g_W + soff_tab[w - 1];
    int Kw  = w << 9;
    int nch = w << 3;                  // K / 64

    uint32_t sb = smem_to_u32(smem);
    int tid = threadIdx.x, wid = tid >> 5, lane = tid & 31;
    int wm = wid >> 2;                 // 0..1 : rows wm*64
    int wn = wid & 3;                  // 0..3 : cols wn*32

    const __half* XB = g_X + ((size_t)b * TP + t0) * H;

    auto load_stage = [&](int c, int s) {
        uint32_t st = sb + (uint32_t)s * 32768u;
        int dw = c >> 3, cc = c & 7;
        #pragma unroll
        for (int q = 0; q < 4; q++) {
            int idx  = q * 256 + tid;  // 0..1023
            int row  = idx >> 3;       // 0..127
            int col8 = idx & 7;
            uint32_t sw = SMEM_SWIZZLE_128B((uint32_t)(row * 128 + col8 * 16));
            CP_ASYNC_16(st + sw,          Abase + (size_t)row * Kw + c * 64 + col8 * 8);
            CP_ASYNC_16(st + 16384u + sw, XB + (size_t)(dw + row) * H + cc * 64 + col8 * 8);
        }
        CP_ASYNC_COMMIT();
    };

    float acc[4][4][4];
    #pragma unroll
    for (int mi = 0; mi < 4; mi++)
        #pragma unroll
        for (int ni = 0; ni < 4; ni++)
            #pragma unroll
            for (int e = 0; e < 4; e++) acc[mi][ni][e] = 0.0f;

    load_stage(0, 0);
    load_stage(1, 1);

    #pragma unroll 1
    for (int c = 0; c < nch; c++) {
        if (c + 2 < nch) { load_stage(c + 2, (c + 2) % 3); CP_ASYNC_WAIT(2); }
        else             { CP_ASYNC_WAIT(0); }
        __syncthreads();

        uint32_t st = sb + (uint32_t)(c % 3) * 32768u;
        #pragma unroll
        for (int ks = 0; ks < 4; ks++) {
            int k0 = ks * 16;
            uint32_t a[4][4];
            #pragma unroll
            for (int mi = 0; mi < 4; mi++) {
                int row = wm * 64 + mi * 16 + ((lane >> 3) & 1) * 8 + (lane & 7);
                int col = k0 + (lane >> 4) * 8;
                ldsm_x4(a[mi], st + SMEM_SWIZZLE_128B((uint32_t)(row * 128 + col * 2)));
            }
            uint32_t bh[2][4];
            #pragma unroll
            for (int nh = 0; nh < 2; nh++) {
                int row = wn * 32 + nh * 16 + (lane >> 4) * 8 + (lane & 7);
                int col = k0 + ((lane >> 3) & 1) * 8;
                ldsm_x4(bh[nh], st + 16384u + SMEM_SWIZZLE_128B((uint32_t)(row * 128 + col * 2)));
            }
            #pragma unroll
            for (int mi = 0; mi < 4; mi++)
                #pragma unroll
                for (int ni = 0; ni < 4; ni++)
                    mma_f16(acc[mi][ni], a[mi], &bh[ni >> 1][(ni & 1) * 2]);
        }
        __syncthreads();
    }

    // Epilogue: masked max over t, + bias, relu floor, atomicMax into g_feat.
    const float* bias = (w == 1) ? b1 : (w == 2) ? b2 : (w == 3) ? b3 : (w == 4) ? b4 : b5;
    float* featb = g_feat + (size_t)b * (5 * NF) + (size_t)(w - 1) * NF;

    #pragma unroll
    for (int mi = 0; mi < 4; mi++) {
        int f0 = wm * 64 + mi * 16 + (lane >> 2);
        float m0 = -1e30f, m1 = -1e30f;
        #pragma unroll
        for (int ni = 0; ni < 4; ni++) {
            int t = t0 + wn * 32 + ni * 8 + (lane & 3) * 2;
            if (t <= tmax)     { m0 = fmaxf(m0, acc[mi][ni][0]); m1 = fmaxf(m1, acc[mi][ni][2]); }
            if (t + 1 <= tmax) { m0 = fmaxf(m0, acc[mi][ni][1]); m1 = fmaxf(m1, acc[mi][ni][3]); }
        }
        #pragma unroll
        for (int o = 1; o <= 2; o <<= 1) {
            m0 = fmaxf(m0, __shfl_xor_sync(0xffffffffu, m0, o));
            m1 = fmaxf(m1, __shfl_xor_sync(0xffffffffu, m1, o));
        }
        if ((lane & 3) == 0) {
            float fa = fmaxf(0.0f, m0 + bias[f0]);
            float fb = fmaxf(0.0f, m1 + bias[f0 + 8]);
            atomicMax((int*)&featb[f0],     __float_as_int(fa));
            atomicMax((int*)&featb[f0 + 8], __float_as_int(fb));
        }
    }
}

// ---------------------------------------------------------------------------
// Collapsed FC: out[b] = sigmoid(feat_b . g_v + g_c). One warp per batch.
// ---------------------------------------------------------------------------
__global__ void __launch_bounds__(1024) fc_kernel(float* __restrict__ out) {
    int warp = threadIdx.x >> 5, lane = threadIdx.x & 31;
    int b = blockIdx.x * 32 + warp;
    if (b >= B) return;
    const float* feat = g_feat + (size_t)b * (5 * NF);
    float s = 0.0f;
    #pragma unroll
    for (int k = 0; k < 20; k++) {
        int j = k * 32 + lane;
        s += feat[j] * g_v[j];
    }
    #pragma unroll
    for (int off = 16; off > 0; off >>= 1)
        s += __shfl_xor_sync(0xffffffffu, s, off);
    if (lane == 0) out[b] = 1.0f / (1.0f + expf(-(s + g_c[0])));
}

// ---------------------------------------------------------------------------
extern "C" void kernel_launch(void* const* d_in, const int* in_sizes, int n_in,
                              void* d_out, int out_size) {
    const float* enc     = (const float*)d_in[0];
    const int*   lengths = (const int*)d_in[1];
    const float* w1 = (const float*)d_in[2];
    const float* cb1 = (const float*)d_in[3];
    const float* w2 = (const float*)d_in[4];
    const float* cb2 = (const float*)d_in[5];
    const float* w3 = (const float*)d_in[6];
    const float* cb3 = (const float*)d_in[7];
    const float* w4 = (const float*)d_in[8];
    const float* cb4 = (const float*)d_in[9];
    const float* w5 = (const float*)d_in[10];
    const float* cb5 = (const float*)d_in[11];
    const float* fc1_w = (const float*)d_in[12];
    const float* fc1_b = (const float*)d_in[13];
    const float* fc2_w = (const float*)d_in[14];
    const float* fc2_b = (const float*)d_in[15];
    float* out = (float*)d_out;

    static bool s_attr_done = false;
    if (!s_attr_done) {
        cudaFuncSetAttribute(gemm_kernel, cudaFuncAttributeMaxDynamicSharedMemorySize,
                             GEMM_SMEM_BYTES);
        s_attr_done = true;
    }

    prep_kernel<<<dim3(16, 4, 228), 256>>>(enc, lengths, w1, w2, w3, w4, w5,
                                           fc1_w, fc1_b, fc2_w, fc2_b);
    gemm_kernel<<<dim3(T / 128, B, 5), 256, GEMM_SMEM_BYTES>>>(lengths, cb1, cb2, cb3, cb4, cb5);
    fc_kernel<<<4, 1024>>>(out);
}

// round 13
// speedup vs baseline: 1.1925x; 1.0913x over previous
#include <cuda_runtime.h>
#include <cuda_fp16.h>
#include <cstdint>
#include <math.h>

#define T 512
#define TP 520            /* T + 8 zero-pad rows for dw-shifted B reads */
#define B 128
#define H 512
#define NF 128
#define FS 5
#define W_ELEMS 983040    /* 128 * 512 * 15 */
#define PAD_ELEMS 524288  /* B * 8 * H */
#define FEAT_ELEMS 81920  /* B * 5 * NF */

// ---------------------------------------------------------------------------
// Scratch (__device__ globals: allocation-guard safe)
// ---------------------------------------------------------------------------
__device__ __align__(16) __half g_W[W_ELEMS];                 // [sec w][f][k=dw*512+h]
__device__ __align__(16) __half g_X[(size_t)B * TP * H];      // X fp16 [b][t][h]
__device__ float g_feat[(size_t)B * 5 * NF];                  // pooled features
__device__ float g_v[5 * NF];                                 // collapsed fc vector
__device__ float g_c[1];                                      // collapsed fc scalar

// ---------------------------------------------------------------------------
// Portable PTX helpers (valid at compute_103 virtual arch)
// ---------------------------------------------------------------------------
__device__ __forceinline__ uint32_t smem_to_u32(const void* p) {
    uint32_t a;
    asm("{ .reg .u64 t; cvta.to.shared.u64 t, %1; cvt.u32.u64 %0, t; }" : "=r"(a) : "l"(p));
    return a;
}
#define SMEM_SWIZZLE_128B(off) ((off) ^ (((off) >> 3) & 0x70))

#define CP_ASYNC_16(dst, src) \
    asm volatile("cp.async.cg.shared.global [%0], [%1], 16;" :: "r"(dst), "l"(src))
#define CP_ASYNC_COMMIT() asm volatile("cp.async.commit_group;" ::: "memory")
#define CP_ASYNC_WAIT(n)  asm volatile("cp.async.wait_group %0;" :: "n"(n) : "memory")

__device__ __forceinline__ void ldsm_x4(uint32_t* r, uint32_t addr) {
    asm volatile("ldmatrix.sync.aligned.m8n8.x4.shared.b16 {%0,%1,%2,%3}, [%4];"
                 : "=r"(r[0]), "=r"(r[1]), "=r"(r[2]), "=r"(r[3]) : "r"(addr));
}

__device__ __forceinline__ void mma_f16(float* c, const uint32_t* a, const uint32_t* b) {
    asm volatile(
        "mma.sync.aligned.m16n8k16.row.col.f32.f16.f16.f32 "
        "{%0,%1,%2,%3}, {%4,%5,%6,%7}, {%8,%9}, {%0,%1,%2,%3};"
        : "+f"(c[0]), "+f"(c[1]), "+f"(c[2]), "+f"(c[3])
        : "r"(a[0]), "r"(a[1]), "r"(a[2]), "r"(a[3]), "r"(b[0]), "r"(b[1]));
}

// ---------------------------------------------------------------------------
// Combined prep kernel. grid (16, 4, 228), block 256.  [Round-8 measured-good]
//  z <  128 : gather+transpose pack of X for batch z; 4 h-subtiles per block
//  z >= 128 : linearized aux: W pack | pad-row zero | feat zero | fc collapse
// ---------------------------------------------------------------------------
__global__ void __launch_bounds__(256) prep_kernel(
    const float* __restrict__ enc, const int* __restrict__ lengths,
    const float* __restrict__ w1, const float* __restrict__ w2,
    const float* __restrict__ w3, const float* __restrict__ w4,
    const float* __restrict__ w5,
    const float* __restrict__ fc1_w, const float* __restrict__ fc1_b,
    const float* __restrict__ fc2_w, const float* __restrict__ fc2_b)
{
    int z = blockIdx.z;
    int tid = threadIdx.x;

    if (z < B) {
        // ---- pack_xt path: tile 32(t) x 128(h) per block, 4 subtiles ----
        __shared__ float tile[32][33];
        int b  = z;
        int L  = lengths[b];
        int Leff = (L > FS) ? L : FS;
        int t0 = blockIdx.x * 32;
        if (t0 >= Leff) return;     // masked-out tiles: stale data harmless
        int wid = tid >> 5, lane = tid & 31;
        int t = t0 + lane;
        size_t encb = (size_t)b * H;

        #pragma unroll 1
        for (int hs = 0; hs < 4; hs++) {
            int h0 = blockIdx.y * 128 + hs * 32;
            #pragma unroll
            for (int k = 0; k < 4; k++) {
                int hl = wid * 4 + k;
                float v = 0.0f;
                if (t < L) {
                    int i = (h0 + hl) * L + t;
                    v = enc[(size_t)(i >> 9) * (B * H) + encb + (i & (H - 1))];
                }
                tile[hl][lane] = v;
            }
            __syncthreads();
            // transposed half2 writes: 2 rows per warp per iter, 16 lanes/row
            #pragma unroll
            for (int it = 0; it < 2; it++) {
                int tl = it * 16 + wid * 2 + (lane >> 4);
                int hh = (lane & 15) * 2;
                __half2 val = __floats2half2_rn(tile[hh][tl], tile[hh + 1][tl]);
                *(__half2*)&g_X[((size_t)b * TP + t0 + tl) * H + h0 + hh] = val;
            }
            __syncthreads();
        }
        return;
    }

    // ---- aux path ----
    int bi = (z - B) * 64 + blockIdx.y * 16 + blockIdx.x;    // 0..6399
    int g  = bi * 256 + tid;

    if (g < W_ELEMS) {
        int idx = g;
        int w, rel;
        if (idx < 65536)       { w = 1; rel = idx; }
        else if (idx < 196608) { w = 2; rel = idx - 65536; }
        else if (idx < 393216) { w = 3; rel = idx - 196608; }
        else if (idx < 655360) { w = 4; rel = idx - 393216; }
        else                   { w = 5; rel = idx - 655360; }
        int Kw = w << 9;
        int f  = rel / Kw;
        int k  = rel - f * Kw;
        int dw = k >> 9;
        int h  = k & 511;
        const float* wp = (w == 1) ? w1 : (w == 2) ? w2 : (w == 3) ? w3 : (w == 4) ? w4 : w5;
        g_W[idx] = __float2half(wp[(size_t)(f * H + h) * w + dw]);
        return;
    }
    int r = g - W_ELEMS;
    if (r < PAD_ELEMS) {            // zero the 8 pad rows per batch
        int b   = r >> 12;          // /(8*H)
        int off = r & 4095;
        g_X[(size_t)b * TP * H + (size_t)T * H + off] = __float2half(0.0f);
        return;
    }
    r -= PAD_ELEMS;
    if (r < FEAT_ELEMS) { g_feat[r] = 0.0f; return; }
    r -= FEAT_ELEMS;
    if (r < 5 * NF) {               // fc collapse: v[j] = sum_o fc2_w[o] * fc1_w[o][j]
        float s = 0.0f;
        #pragma unroll 4
        for (int o = 0; o < 100; o++) s += fc2_w[o] * fc1_w[(size_t)o * (5 * NF) + r];
        g_v[r] = s;
        if (r == 0) {
            float c = fc2_b[0];
            for (int o = 0; o < 100; o++) c += fc2_w[o] * fc1_b[o];
            g_c[0] = c;
        }
    }
}

// ---------------------------------------------------------------------------
// Fused conv-GEMM + bias + relu + masked max-pool (single-pass fp16).
// Section w: out(f,t) = sum_{dw<w, h} W[f,h,dw] * X[h, t+dw]  (K = 512*w)
// CTA tile 128(f) x 64(t), 128 threads, 4 warps in 2x2 — warp tile stays
// 64x32 (identical measured-good inner instruction stream; geometry only).
// K-chunk 64, 3-stage cp.async. Stage: A 16KB | B 8KB = 24KB; 3 = 72KB.
// LPT order: blockIdx.z slowest = w, with w=5 scheduled first.
// ---------------------------------------------------------------------------
#define GEMM_SMEM_BYTES 73728

__global__ void __launch_bounds__(128) gemm_kernel(
    const int* __restrict__ lengths,
    const float* __restrict__ b1, const float* __restrict__ b2,
    const float* __restrict__ b3, const float* __restrict__ b4,
    const float* __restrict__ b5)
{
    extern __shared__ char smem[];
    int b = blockIdx.y;
    int w = 5 - blockIdx.z;            // LPT: longest CTAs (w=5) launch first
    int L = lengths[b];
    int Leff = (L > FS) ? L : FS;
    int tmax = Leff - w;               // inclusive valid t
    int t0 = blockIdx.x * 64;
    if (t0 > tmax) return;

    const int soff_tab[5] = { 0, 65536, 196608, 393216, 655360 };
    const __half* Abase = g_W + soff_tab[w - 1];
    int Kw  = w << 9;
    int nch = w << 3;                  // K / 64

    uint32_t sb = smem_to_u32(smem);
    int tid = threadIdx.x, wid = tid >> 5, lane = tid & 31;
    int wm = wid >> 1;                 // 0..1 : rows wm*64
    int wn = wid & 1;                  // 0..1 : cols wn*32

    const __half* XB = g_X + ((size_t)b * TP + t0) * H;

    auto load_stage = [&](int c, int s) {
        uint32_t st = sb + (uint32_t)s * 24576u;
        int dw = c >> 3, cc = c & 7;
        // A: 128 rows x 64 half = 1024 x 16B, 8 per thread
        #pragma unroll
        for (int q = 0; q < 8; q++) {
            int idx  = q * 128 + tid;  // 0..1023
            int row  = idx >> 3;       // 0..127
            int col8 = idx & 7;
            uint32_t sw = SMEM_SWIZZLE_128B((uint32_t)(row * 128 + col8 * 16));
            CP_ASYNC_16(st + sw, Abase + (size_t)row * Kw + c * 64 + col8 * 8);
        }
        // B: 64 rows x 64 half = 512 x 16B, 4 per thread
        #pragma unroll
        for (int q = 0; q < 4; q++) {
            int idx  = q * 128 + tid;  // 0..511
            int row  = idx >> 3;       // 0..63
            int col8 = idx & 7;
            uint32_t sw = SMEM_SWIZZLE_128B((uint32_t)(row * 128 + col8 * 16));
            CP_ASYNC_16(st + 16384u + sw, XB + (size_t)(dw + row) * H + cc * 64 + col8 * 8);
        }
        CP_ASYNC_COMMIT();
    };

    float acc[4][4][4];
    #pragma unroll
    for (int mi = 0; mi < 4; mi++)
        #pragma unroll
        for (int ni = 0; ni < 4; ni++)
            #pragma unroll
            for (int e = 0; e < 4; e++) acc[mi][ni][e] = 0.0f;

    load_stage(0, 0);
    load_stage(1, 1);

    #pragma unroll 1
    for (int c = 0; c < nch; c++) {
        if (c + 2 < nch) { load_stage(c + 2, (c + 2) % 3); CP_ASYNC_WAIT(2); }
        else             { CP_ASYNC_WAIT(0); }
        __syncthreads();

        uint32_t st = sb + (uint32_t)(c % 3) * 24576u;
        #pragma unroll
        for (int ks = 0; ks < 4; ks++) {
            int k0 = ks * 16;
            uint32_t a[4][4];
            #pragma unroll
            for (int mi = 0; mi < 4; mi++) {
                int row = wm * 64 + mi * 16 + ((lane >> 3) & 1) * 8 + (lane & 7);
                int col = k0 + (lane >> 4) * 8;
                ldsm_x4(a[mi], st + SMEM_SWIZZLE_128B((uint32_t)(row * 128 + col * 2)));
            }
            uint32_t bh[2][4];
            #pragma unroll
            for (int nh = 0; nh < 2; nh++) {
                int row = wn * 32 + nh * 16 + (lane >> 4) * 8 + (lane & 7);
                int col = k0 + ((lane >> 3) & 1) * 8;
                ldsm_x4(bh[nh], st + 16384u + SMEM_SWIZZLE_128B((uint32_t)(row * 128 + col * 2)));
            }
            #pragma unroll
            for (int mi = 0; mi < 4; mi++)
                #pragma unroll
                for (int ni = 0; ni < 4; ni++)
                    mma_f16(acc[mi][ni], a[mi], &bh[ni >> 1][(ni & 1) * 2]);
        }
        __syncthreads();
    }

    // Epilogue: masked max over t, + bias, relu floor, atomicMax into g_feat.
    const float* bias = (w == 1) ? b1 : (w == 2) ? b2 : (w == 3) ? b3 : (w == 4) ? b4 : b5;
    float* featb = g_feat + (size_t)b * (5 * NF) + (size_t)(w - 1) * NF;

    #pragma unroll
    for (int mi = 0; mi < 4; mi++) {
        int f0 = wm * 64 + mi * 16 + (lane >> 2);
        float m0 = -1e30f, m1 = -1e30f;
        #pragma unroll
        for (int ni = 0; ni < 4; ni++) {
            int t = t0 + wn * 32 + ni * 8 + (lane & 3) * 2;
            if (t <= tmax)     { m0 = fmaxf(m0, acc[mi][ni][0]); m1 = fmaxf(m1, acc[mi][ni][2]); }
            if (t + 1 <= tmax) { m0 = fmaxf(m0, acc[mi][ni][1]); m1 = fmaxf(m1, acc[mi][ni][3]); }
        }
        #pragma unroll
        for (int o = 1; o <= 2; o <<= 1) {
            m0 = fmaxf(m0, __shfl_xor_sync(0xffffffffu, m0, o));
            m1 = fmaxf(m1, __shfl_xor_sync(0xffffffffu, m1, o));
        }
        if ((lane & 3) == 0) {
            float fa = fmaxf(0.0f, m0 + bias[f0]);
            float fb = fmaxf(0.0f, m1 + bias[f0 + 8]);
            atomicMax((int*)&featb[f0],     __float_as_int(fa));
            atomicMax((int*)&featb[f0 + 8], __float_as_int(fb));
        }
    }
}

// ---------------------------------------------------------------------------
// Collapsed FC: out[b] = sigmoid(feat_b . g_v + g_c). One warp per batch.
// ---------------------------------------------------------------------------
__global__ void __launch_bounds__(1024) fc_kernel(float* __restrict__ out) {
    int warp = threadIdx.x >> 5, lane = threadIdx.x & 31;
    int b = blockIdx.x * 32 + warp;
    if (b >= B) return;
    const float* feat = g_feat + (size_t)b * (5 * NF);
    float s = 0.0f;
    #pragma unroll
    for (int k = 0; k < 20; k++) {
        int j = k * 32 + lane;
        s += feat[j] * g_v[j];
    }
    #pragma unroll
    for (int off = 16; off > 0; off >>= 1)
        s += __shfl_xor_sync(0xffffffffu, s, off);
    if (lane == 0) out[b] = 1.0f / (1.0f + expf(-(s + g_c[0])));
}

// ---------------------------------------------------------------------------
extern "C" void kernel_launch(void* const* d_in, const int* in_sizes, int n_in,
                              void* d_out, int out_size) {
    const float* enc     = (const float*)d_in[0];
    const int*   lengths = (const int*)d_in[1];
    const float* w1 = (const float*)d_in[2];
    const float* cb1 = (const float*)d_in[3];
    const float* w2 = (const float*)d_in[4];
    const float* cb2 = (const float*)d_in[5];
    const float* w3 = (const float*)d_in[6];
    const float* cb3 = (const float*)d_in[7];
    const float* w4 = (const float*)d_in[8];
    const float* cb4 = (const float*)d_in[9];
    const float* w5 = (const float*)d_in[10];
    const float* cb5 = (const float*)d_in[11];
    const float* fc1_w = (const float*)d_in[12];
    const float* fc1_b = (const float*)d_in[13];
    const float* fc2_w = (const float*)d_in[14];
    const float* fc2_b = (const float*)d_in[15];
    float* out = (float*)d_out;

    static bool s_attr_done = false;
    if (!s_attr_done) {
        cudaFuncSetAttribute(gemm_kernel, cudaFuncAttributeMaxDynamicSharedMemorySize,
                             GEMM_SMEM_BYTES);
        s_attr_done = true;
    }

    prep_kernel<<<dim3(16, 4, 228), 256>>>(enc, lengths, w1, w2, w3, w4, w5,
                                           fc1_w, fc1_b, fc2_w, fc2_b);
    gemm_kernel<<<dim3(T / 64, B, 5), 128, GEMM_SMEM_BYTES>>>(lengths, cb1, cb2, cb3, cb4, cb5);
    fc_kernel<<<4, 1024>>>(out);
}

// round 14
// speedup vs baseline: 1.2204x; 1.0234x over previous
#include <cuda_runtime.h>
#include <cuda_fp16.h>
#include <cstdint>
#include <math.h>

#define T 512
#define TP 520            /* T + 8 zero-pad rows for dw-shifted B reads */
#define B 128
#define H 512
#define NF 128
#define FS 5
#define W_ELEMS 983040    /* 128 * 512 * 15 */
#define PAD_ELEMS 524288  /* B * 8 * H */
#define FEAT_ELEMS 81920  /* B * 5 * NF */

// ---------------------------------------------------------------------------
// Scratch (__device__ globals: allocation-guard safe)
// ---------------------------------------------------------------------------
__device__ __align__(16) __half g_W[W_ELEMS];                 // [sec w][f][k=dw*512+h]
__device__ __align__(16) __half g_X[(size_t)B * TP * H];      // X fp16 [b][t][h]
__device__ float g_feat[(size_t)B * 5 * NF];                  // pooled features
__device__ float g_v[5 * NF];                                 // collapsed fc vector
__device__ float g_c[1];                                      // collapsed fc scalar

// ---------------------------------------------------------------------------
// Portable PTX helpers (valid at compute_103 virtual arch)
// ---------------------------------------------------------------------------
__device__ __forceinline__ uint32_t smem_to_u32(const void* p) {
    uint32_t a;
    asm("{ .reg .u64 t; cvta.to.shared.u64 t, %1; cvt.u32.u64 %0, t; }" : "=r"(a) : "l"(p));
    return a;
}
#define SMEM_SWIZZLE_128B(off) ((off) ^ (((off) >> 3) & 0x70))

#define CP_ASYNC_16(dst, src) \
    asm volatile("cp.async.cg.shared.global [%0], [%1], 16;" :: "r"(dst), "l"(src))
#define CP_ASYNC_COMMIT() asm volatile("cp.async.commit_group;" ::: "memory")
#define CP_ASYNC_WAIT(n)  asm volatile("cp.async.wait_group %0;" :: "n"(n) : "memory")

__device__ __forceinline__ void ldsm_x4(uint32_t* r, uint32_t addr) {
    asm volatile("ldmatrix.sync.aligned.m8n8.x4.shared.b16 {%0,%1,%2,%3}, [%4];"
                 : "=r"(r[0]), "=r"(r[1]), "=r"(r[2]), "=r"(r[3]) : "r"(addr));
}

__device__ __forceinline__ void mma_f16(float* c, const uint32_t* a, const uint32_t* b) {
    asm volatile(
        "mma.sync.aligned.m16n8k16.row.col.f32.f16.f16.f32 "
        "{%0,%1,%2,%3}, {%4,%5,%6,%7}, {%8,%9}, {%0,%1,%2,%3};"
        : "+f"(c[0]), "+f"(c[1]), "+f"(c[2]), "+f"(c[3])
        : "r"(a[0]), "r"(a[1]), "r"(a[2]), "r"(a[3]), "r"(b[0]), "r"(b[1]));
}

// ---------------------------------------------------------------------------
// Combined prep kernel. grid (16, 4, 228), block 256.
//  z <  128 : gather+transpose pack of X for batch z.
//             ALL 16 gathers issued up-front (MLP 16) into registers, staged
//             into 4 parallel smem tiles, ONE barrier, then all stores.
//  z >= 128 : linearized aux: W pack | pad-row zero | feat zero | fc collapse
// ---------------------------------------------------------------------------
__global__ void __launch_bounds__(256) prep_kernel(
    const float* __restrict__ enc, const int* __restrict__ lengths,
    const float* __restrict__ w1, const float* __restrict__ w2,
    const float* __restrict__ w3, const float* __restrict__ w4,
    const float* __restrict__ w5,
    const float* __restrict__ fc1_w, const float* __restrict__ fc1_b,
    const float* __restrict__ fc2_w, const float* __restrict__ fc2_b)
{
    int z = blockIdx.z;
    int tid = threadIdx.x;

    if (z < B) {
        // ---- pack_xt path: tile 32(t) x 128(h) per block ----
        __shared__ float tile[4][32][33];
        int b  = z;
        int L  = lengths[b];
        int Leff = (L > FS) ? L : FS;
        int t0 = blockIdx.x * 32;
        if (t0 >= Leff) return;     // masked-out tiles: stale data harmless
        int wid = tid >> 5, lane = tid & 31;
        int t = t0 + lane;
        size_t encb = (size_t)b * H;
        bool tin = (t < L);

        // Phase 1: issue all 16 gathers back-to-back (deep MLP)
        float vals[4][4];
        #pragma unroll
        for (int hs = 0; hs < 4; hs++) {
            #pragma unroll
            for (int k = 0; k < 4; k++) {
                int hl = wid * 4 + k;
                int h  = blockIdx.y * 128 + hs * 32 + hl;
                float v = 0.0f;
                if (tin) {
                    int i = h * L + t;
                    v = enc[(size_t)(i >> 9) * (B * H) + encb + (i & (H - 1))];
                }
                vals[hs][k] = v;
            }
        }
        // Phase 2: stage into smem, one barrier
        #pragma unroll
        for (int hs = 0; hs < 4; hs++)
            #pragma unroll
            for (int k = 0; k < 4; k++)
                tile[hs][wid * 4 + k][lane] = vals[hs][k];
        __syncthreads();

        // Phase 3: all transposed half2 stores
        #pragma unroll
        for (int hs = 0; hs < 4; hs++) {
            int h0 = blockIdx.y * 128 + hs * 32;
            #pragma unroll
            for (int it = 0; it < 2; it++) {
                int tl = it * 16 + wid * 2 + (lane >> 4);
                int hh = (lane & 15) * 2;
                __half2 val = __floats2half2_rn(tile[hs][hh][tl], tile[hs][hh + 1][tl]);
                *(__half2*)&g_X[((size_t)b * TP + t0 + tl) * H + h0 + hh] = val;
            }
        }
        return;
    }

    // ---- aux path ----
    int bi = (z - B) * 64 + blockIdx.y * 16 + blockIdx.x;    // 0..6399
    int g  = bi * 256 + tid;

    if (g < W_ELEMS) {
        int idx = g;
        int w, rel;
        if (idx < 65536)       { w = 1; rel = idx; }
        else if (idx < 196608) { w = 2; rel = idx - 65536; }
        else if (idx < 393216) { w = 3; rel = idx - 196608; }
        else if (idx < 655360) { w = 4; rel = idx - 393216; }
        else                   { w = 5; rel = idx - 655360; }
        int Kw = w << 9;
        int f  = rel / Kw;
        int k  = rel - f * Kw;
        int dw = k >> 9;
        int h  = k & 511;
        const float* wp = (w == 1) ? w1 : (w == 2) ? w2 : (w == 3) ? w3 : (w == 4) ? w4 : w5;
        g_W[idx] = __float2half(wp[(size_t)(f * H + h) * w + dw]);
        return;
    }
    int r = g - W_ELEMS;
    if (r < PAD_ELEMS) {            // zero the 8 pad rows per batch
        int b   = r >> 12;          // /(8*H)
        int off = r & 4095;
        g_X[(size_t)b * TP * H + (size_t)T * H + off] = __float2half(0.0f);
        return;
    }
    r -= PAD_ELEMS;
    if (r < FEAT_ELEMS) { g_feat[r] = 0.0f; return; }
    r -= FEAT_ELEMS;
    if (r < 5 * NF) {               // fc collapse: v[j] = sum_o fc2_w[o] * fc1_w[o][j]
        float s = 0.0f;
        #pragma unroll 4
        for (int o = 0; o < 100; o++) s += fc2_w[o] * fc1_w[(size_t)o * (5 * NF) + r];
        g_v[r] = s;
        if (r == 0) {
            float c = fc2_b[0];
            for (int o = 0; o < 100; o++) c += fc2_w[o] * fc1_b[o];
            g_c[0] = c;
        }
    }
}

// ---------------------------------------------------------------------------
// Fused conv-GEMM + bias + relu + masked max-pool (single-pass fp16).
// [Round-13 measured-good — UNCHANGED]
// Section w: out(f,t) = sum_{dw<w, h} W[f,h,dw] * X[h, t+dw]  (K = 512*w)
// CTA tile 128(f) x 64(t), 128 threads, 4 warps in 2x2, warp tile 64x32.
// K-chunk 64, 3-stage cp.async. Stage: A 16KB | B 8KB = 24KB; 3 = 72KB.
// LPT order: blockIdx.z slowest = w, with w=5 scheduled first.
// ---------------------------------------------------------------------------
#define GEMM_SMEM_BYTES 73728

__global__ void __launch_bounds__(128) gemm_kernel(
    const int* __restrict__ lengths,
    const float* __restrict__ b1, const float* __restrict__ b2,
    const float* __restrict__ b3, const float* __restrict__ b4,
    const float* __restrict__ b5)
{
    extern __shared__ char smem[];
    int b = blockIdx.y;
    int w = 5 - blockIdx.z;            // LPT: longest CTAs (w=5) launch first
    int L = lengths[b];
    int Leff = (L > FS) ? L : FS;
    int tmax = Leff - w;               // inclusive valid t
    int t0 = blockIdx.x * 64;
    if (t0 > tmax) return;

    const int soff_tab[5] = { 0, 65536, 196608, 393216, 655360 };
    const __half* Abase = g_W + soff_tab[w - 1];
    int Kw  = w << 9;
    int nch = w << 3;                  // K / 64

    uint32_t sb = smem_to_u32(smem);
    int tid = threadIdx.x, wid = tid >> 5, lane = tid & 31;
    int wm = wid >> 1;                 // 0..1 : rows wm*64
    int wn = wid & 1;                  // 0..1 : cols wn*32

    const __half* XB = g_X + ((size_t)b * TP + t0) * H;

    auto load_stage = [&](int c, int s) {
        uint32_t st = sb + (uint32_t)s * 24576u;
        int dw = c >> 3, cc = c & 7;
        // A: 128 rows x 64 half = 1024 x 16B, 8 per thread
        #pragma unroll
        for (int q = 0; q < 8; q++) {
            int idx  = q * 128 + tid;  // 0..1023
            int row  = idx >> 3;       // 0..127
            int col8 = idx & 7;
            uint32_t sw = SMEM_SWIZZLE_128B((uint32_t)(row * 128 + col8 * 16));
            CP_ASYNC_16(st + sw, Abase + (size_t)row * Kw + c * 64 + col8 * 8);
        }
        // B: 64 rows x 64 half = 512 x 16B, 4 per thread
        #pragma unroll
        for (int q = 0; q < 4; q++) {
            int idx  = q * 128 + tid;  // 0..511
            int row  = idx >> 3;       // 0..63
            int col8 = idx & 7;
            uint32_t sw = SMEM_SWIZZLE_128B((uint32_t)(row * 128 + col8 * 16));
            CP_ASYNC_16(st + 16384u + sw, XB + (size_t)(dw + row) * H + cc * 64 + col8 * 8);
        }
        CP_ASYNC_COMMIT();
    };

    float acc[4][4][4];
    #pragma unroll
    for (int mi = 0; mi < 4; mi++)
        #pragma unroll
        for (int ni = 0; ni < 4; ni++)
            #pragma unroll
            for (int e = 0; e < 4; e++) acc[mi][ni][e] = 0.0f;

    load_stage(0, 0);
    load_stage(1, 1);

    #pragma unroll 1
    for (int c = 0; c < nch; c++) {
        if (c + 2 < nch) { load_stage(c + 2, (c + 2) % 3); CP_ASYNC_WAIT(2); }
        else             { CP_ASYNC_WAIT(0); }
        __syncthreads();

        uint32_t st = sb + (uint32_t)(c % 3) * 24576u;
        #pragma unroll
        for (int ks = 0; ks < 4; ks++) {
            int k0 = ks * 16;
            uint32_t a[4][4];
            #pragma unroll
            for (int mi = 0; mi < 4; mi++) {
                int row = wm * 64 + mi * 16 + ((lane >> 3) & 1) * 8 + (lane & 7);
                int col = k0 + (lane >> 4) * 8;
                ldsm_x4(a[mi], st + SMEM_SWIZZLE_128B((uint32_t)(row * 128 + col * 2)));
            }
            uint32_t bh[2][4];
            #pragma unroll
            for (int nh = 0; nh < 2; nh++) {
                int row = wn * 32 + nh * 16 + (lane >> 4) * 8 + (lane & 7);
                int col = k0 + ((lane >> 3) & 1) * 8;
                ldsm_x4(bh[nh], st + 16384u + SMEM_SWIZZLE_128B((uint32_t)(row * 128 + col * 2)));
            }
            #pragma unroll
            for (int mi = 0; mi < 4; mi++)
                #pragma unroll
                for (int ni = 0; ni < 4; ni++)
                    mma_f16(acc[mi][ni], a[mi], &bh[ni >> 1][(ni & 1) * 2]);
        }
        __syncthreads();
    }

    // Epilogue: masked max over t, + bias, relu floor, atomicMax into g_feat.
    const float* bias = (w == 1) ? b1 : (w == 2) ? b2 : (w == 3) ? b3 : (w == 4) ? b4 : b5;
    float* featb = g_feat + (size_t)b * (5 * NF) + (size_t)(w - 1) * NF;

    #pragma unroll
    for (int mi = 0; mi < 4; mi++) {
        int f0 = wm * 64 + mi * 16 + (lane >> 2);
        float m0 = -1e30f, m1 = -1e30f;
        #pragma unroll
        for (int ni = 0; ni < 4; ni++) {
            int t = t0 + wn * 32 + ni * 8 + (lane & 3) * 2;
            if (t <= tmax)     { m0 = fmaxf(m0, acc[mi][ni][0]); m1 = fmaxf(m1, acc[mi][ni][2]); }
            if (t + 1 <= tmax) { m0 = fmaxf(m0, acc[mi][ni][1]); m1 = fmaxf(m1, acc[mi][ni][3]); }
        }
        #pragma unroll
        for (int o = 1; o <= 2; o <<= 1) {
            m0 = fmaxf(m0, __shfl_xor_sync(0xffffffffu, m0, o));
            m1 = fmaxf(m1, __shfl_xor_sync(0xffffffffu, m1, o));
        }
        if ((lane & 3) == 0) {
            float fa = fmaxf(0.0f, m0 + bias[f0]);
            float fb = fmaxf(0.0f, m1 + bias[f0 + 8]);
            atomicMax((int*)&featb[f0],     __float_as_int(fa));
            atomicMax((int*)&featb[f0 + 8], __float_as_int(fb));
        }
    }
}

// ---------------------------------------------------------------------------
// Collapsed FC: out[b] = sigmoid(feat_b . g_v + g_c). One warp per batch.
// ---------------------------------------------------------------------------
__global__ void __launch_bounds__(1024) fc_kernel(float* __restrict__ out) {
    int warp = threadIdx.x >> 5, lane = threadIdx.x & 31;
    int b = blockIdx.x * 32 + warp;
    if (b >= B) return;
    const float* feat = g_feat + (size_t)b * (5 * NF);
    float s = 0.0f;
    #pragma unroll
    for (int k = 0; k < 20; k++) {
        int j = k * 32 + lane;
        s += feat[j] * g_v[j];
    }
    #pragma unroll
    for (int off = 16; off > 0; off >>= 1)
        s += __shfl_xor_sync(0xffffffffu, s, off);
    if (lane == 0) out[b] = 1.0f / (1.0f + expf(-(s + g_c[0])));
}

// ---------------------------------------------------------------------------
extern "C" void kernel_launch(void* const* d_in, const int* in_sizes, int n_in,
                              void* d_out, int out_size) {
    const float* enc     = (const float*)d_in[0];
    const int*   lengths = (const int*)d_in[1];
    const float* w1 = (const float*)d_in[2];
    const float* cb1 = (const float*)d_in[3];
    const float* w2 = (const float*)d_in[4];
    const float* cb2 = (const float*)d_in[5];
    const float* w3 = (const float*)d_in[6];
    const float* cb3 = (const float*)d_in[7];
    const float* w4 = (const float*)d_in[8];
    const float* cb4 = (const float*)d_in[9];
    const float* w5 = (const float*)d_in[10];
    const float* cb5 = (const float*)d_in[11];
    const float* fc1_w = (const float*)d_in[12];
    const float* fc1_b = (const float*)d_in[13];
    const float* fc2_w = (const float*)d_in[14];
    const float* fc2_b = (const float*)d_in[15];
    float* out = (float*)d_out;

    static bool s_attr_done = false;
    if (!s_attr_done) {
        cudaFuncSetAttribute(gemm_kernel, cudaFuncAttributeMaxDynamicSharedMemorySize,
                             GEMM_SMEM_BYTES);
        s_attr_done = true;
    }

    prep_kernel<<<dim3(16, 4, 228), 256>>>(enc, lengths, w1, w2, w3, w4, w5,
                                           fc1_w, fc1_b, fc2_w, fc2_b);
    gemm_kernel<<<dim3(T / 64, B, 5), 128, GEMM_SMEM_BYTES>>>(lengths, cb1, cb2, cb3, cb4, cb5);
    fc_kernel<<<4, 1024>>>(out);
}